// round 5
// baseline (speedup 1.0000x reference)
#include <cuda_runtime.h>
#include <cuda_bf16.h>
#include <cstdint>
#include <math.h>

// Problem constants
#define B_  2
#define S_  2048
#define HID 2048
#define NH  16
#define HD  128
#define HALF 64
#define ROWS (B_ * S_)            // 4096
#define QKV_W (3 * HID)           // 6144
#define EPS 1e-5f
#define SCALE 0.08838834764831845f   // 1/sqrt(128)

// Scratch (device-global; no runtime allocation allowed)
__device__ float g_qkv[(size_t)ROWS * QKV_W];            // gemm1 out (fp32)
__device__ float g_cos[S_ * HALF];
__device__ float g_sin[S_ * HALF];
__device__ __nv_bfloat16 g_a_hi[(size_t)ROWS * HID];     // gemm A hi plane (x; then O)
__device__ __nv_bfloat16 g_a_lo[(size_t)ROWS * HID];
__device__ __nv_bfloat16 g_b_hi[(size_t)QKV_W * HID];    // gemm B hi plane (w_in; then w_out)
__device__ __nv_bfloat16 g_b_lo[(size_t)QKV_W * HID];
__device__ __nv_bfloat16 g_q_hi[(size_t)ROWS * HID];
__device__ __nv_bfloat16 g_q_lo[(size_t)ROWS * HID];
__device__ __nv_bfloat16 g_k_hi[(size_t)ROWS * HID];
__device__ __nv_bfloat16 g_k_lo[(size_t)ROWS * HID];
__device__ __nv_bfloat16 g_vt_hi[(size_t)ROWS * HID];    // [b][h][d][s]
__device__ __nv_bfloat16 g_vt_lo[(size_t)ROWS * HID];

__device__ __forceinline__ uint32_t smem_u32(const void* p) {
    uint32_t a;
    asm("{ .reg .u64 t; cvta.to.shared.u64 t, %1; cvt.u32.u64 %0, t; }" : "=r"(a) : "l"(p));
    return a;
}
#define SWZ(x) ((x) ^ (((x) >> 3) & 0x70))

__device__ __forceinline__ void ldsm_x4(uint32_t* r, uint32_t addr) {
    asm volatile("ldmatrix.sync.aligned.m8n8.x4.shared.b16 {%0,%1,%2,%3}, [%4];"
                 : "=r"(r[0]), "=r"(r[1]), "=r"(r[2]), "=r"(r[3]) : "r"(addr));
}
__device__ __forceinline__ void mma_bf16(float* c, const uint32_t* a,
                                         uint32_t b0, uint32_t b1) {
    asm volatile(
        "mma.sync.aligned.m16n8k16.row.col.f32.bf16.bf16.f32 "
        "{%0,%1,%2,%3}, {%4,%5,%6,%7}, {%8,%9}, {%0,%1,%2,%3};"
        : "+f"(c[0]), "+f"(c[1]), "+f"(c[2]), "+f"(c[3])
        : "r"(a[0]), "r"(a[1]), "r"(a[2]), "r"(a[3]), "r"(b0), "r"(b1));
}
__device__ __forceinline__ uint32_t pack_bf16x2(float lo, float hi) {
    uint32_t r;
    asm("cvt.rn.bf16x2.f32 %0, %1, %2;" : "=r"(r) : "f"(hi), "f"(lo));
    return r;
}

// ---------------------------------------------------------------------------
// RoPE table
// ---------------------------------------------------------------------------
__global__ void rope_table_kernel() {
    int idx = blockIdx.x * blockDim.x + threadIdx.x;
    if (idx >= S_ * HALF) return;
    int s = idx >> 6;
    int j = idx & 63;
    float freq = powf(10000.0f, -(float)j * (1.0f / 64.0f));
    float sn, cs;
    sincosf((float)s * freq, &sn, &cs);
    g_cos[idx] = cs;
    g_sin[idx] = sn;
}

// ---------------------------------------------------------------------------
// hi/lo split: fp32 -> two bf16 planes (flat)
// ---------------------------------------------------------------------------
__global__ void __launch_bounds__(256) split2_kernel(
    const float* __restrict__ src, __nv_bfloat16* __restrict__ hi,
    __nv_bfloat16* __restrict__ lo, int n4)
{
    int i = blockIdx.x * blockDim.x + threadIdx.x;
    if (i >= n4) return;
    float4 v = ((const float4*)src)[i];
    float vv[4] = {v.x, v.y, v.z, v.w};
    uint64_t hp = 0, lp = 0;
#pragma unroll
    for (int q = 0; q < 4; q++) {
        __nv_bfloat16 h = __float2bfloat16(vv[q]);
        __nv_bfloat16 l = __float2bfloat16(vv[q] - __bfloat162float(h));
        hp |= (uint64_t)__bfloat16_as_ushort(h) << (q * 16);
        lp |= (uint64_t)__bfloat16_as_ushort(l) << (q * 16);
    }
    *(uint64_t*)(hi + (size_t)i * 4) = hp;
    *(uint64_t*)(lo + (size_t)i * 4) = lp;
}

// ---------------------------------------------------------------------------
// 3-term split GEMM via mma.sync:
//   C[M,N] = Ah*Bh^T + Ah*Bl^T + Al*Bh^T      (all operands [*,2048] bf16)
// Block 128x256, BK=64, 2-stage cp.async (96KB/stage), 256 thr, 8 warps 64x64.
// Fragment reuse: Ah used with Bh+Bl, Bh used with Ah+Al.
// ---------------------------------------------------------------------------
#define BM 128
#define BN 256
#define BK 64
#define NK2 (HID / BK)            // 32
#define SAH 0
#define SAL 16384
#define SBH 32768
#define SBL 65536
#define STG2 98304
#define GEMM_SMEM (2 * STG2)      // 196608

__global__ void __launch_bounds__(256, 1) gemm_mma2(
    const __nv_bfloat16* __restrict__ Ah, const __nv_bfloat16* __restrict__ Al,
    const __nv_bfloat16* __restrict__ Bh, const __nv_bfloat16* __restrict__ Bl,
    float* __restrict__ C, int M, int N)
{
    extern __shared__ char smem[];
    const uint32_t sb = smem_u32(smem);
    const int tid = threadIdx.x;
    const int wid = tid >> 5, lid = tid & 31;
    const int tiles_m = M / BM;
    const int m0 = (blockIdx.x % tiles_m) * BM;
    const int n0 = (blockIdx.x / tiles_m) * BN;
    const int wm = (wid & 1) * 64;
    const int wn = (wid >> 1) * 64;
    const int lrow = lid & 15;
    const int lhi = (lid >> 4) * 16;

#define LOAD_STAGE2(st, kt) do {                                               \
    uint32_t sbase = sb + (st) * STG2;                                         \
    _Pragma("unroll")                                                          \
    for (int u = 0; u < 24; u++) {                                             \
        int c = tid + u * 256;                                                 \
        const __nv_bfloat16* gp;                                               \
        uint32_t dst;                                                          \
        if (c < 2048) {                                                        \
            int plane = c >> 10;                                               \
            int cc = c & 1023;                                                 \
            int r = cc >> 3, c16 = cc & 7;                                     \
            gp = (plane ? Al : Ah) + (size_t)(m0 + r) * HID + (kt) * BK + c16 * 8; \
            dst = sbase + (plane ? SAL : SAH) + SWZ(r * 128 + c16 * 16);       \
        } else {                                                               \
            int cc = c - 2048;                                                 \
            int plane = cc >> 11;                                              \
            int c2 = cc & 2047;                                                \
            int r = c2 >> 3, c16 = c2 & 7;                                     \
            gp = (plane ? Bl : Bh) + (size_t)(n0 + r) * HID + (kt) * BK + c16 * 8; \
            dst = sbase + (plane ? SBL : SBH) + SWZ(r * 128 + c16 * 16);       \
        }                                                                      \
        asm volatile("cp.async.cg.shared.global [%0], [%1], 16;"               \
                     :: "r"(dst), "l"(gp) : "memory");                         \
    }                                                                          \
} while (0)

    LOAD_STAGE2(0, 0);
    asm volatile("cp.async.commit_group;" ::: "memory");

    float acc[4][8][4];
#pragma unroll
    for (int mt = 0; mt < 4; mt++)
#pragma unroll
        for (int nt = 0; nt < 8; nt++)
#pragma unroll
            for (int q = 0; q < 4; q++) acc[mt][nt][q] = 0.0f;

    for (int kt = 0; kt < NK2; kt++) {
        if (kt + 1 < NK2) LOAD_STAGE2((kt + 1) & 1, kt + 1);
        asm volatile("cp.async.commit_group;" ::: "memory");
        asm volatile("cp.async.wait_group 1;" ::: "memory");
        __syncthreads();

        const uint32_t sbase = sb + (kt & 1) * STG2;

#pragma unroll
        for (int ks = 0; ks < 4; ks++) {
            const int cb = ks * 32 + lhi;
            uint32_t ahf[4][4], alf[4][4];
#pragma unroll
            for (int mt = 0; mt < 4; mt++) {
                int row = wm + mt * 16 + lrow;
                uint32_t off = row * 128 + (cb ^ ((row & 7) * 16));
                ldsm_x4(ahf[mt], sbase + SAH + off);
                ldsm_x4(alf[mt], sbase + SAL + off);
            }
#pragma unroll
            for (int np = 0; np < 4; np++) {
                int brow = wn + np * 16 + lrow;
                uint32_t boff = brow * 128 + (cb ^ ((brow & 7) * 16));
                uint32_t bh4[4];
                ldsm_x4(bh4, sbase + SBH + boff);
#pragma unroll
                for (int mt = 0; mt < 4; mt++) {
                    mma_bf16(acc[mt][np * 2 + 0], ahf[mt], bh4[0], bh4[2]);
                    mma_bf16(acc[mt][np * 2 + 1], ahf[mt], bh4[1], bh4[3]);
                    mma_bf16(acc[mt][np * 2 + 0], alf[mt], bh4[0], bh4[2]);
                    mma_bf16(acc[mt][np * 2 + 1], alf[mt], bh4[1], bh4[3]);
                }
                uint32_t bl4[4];
                ldsm_x4(bl4, sbase + SBL + boff);
#pragma unroll
                for (int mt = 0; mt < 4; mt++) {
                    mma_bf16(acc[mt][np * 2 + 0], ahf[mt], bl4[0], bl4[2]);
                    mma_bf16(acc[mt][np * 2 + 1], ahf[mt], bl4[1], bl4[3]);
                }
            }
        }
        __syncthreads();
    }

    const int er = m0 + wm + (lid >> 2);
    const int ec = n0 + wn + (lid & 3) * 2;
#pragma unroll
    for (int mt = 0; mt < 4; mt++)
#pragma unroll
        for (int nt = 0; nt < 8; nt++) {
            float* c0 = C + (size_t)(er + mt * 16) * N + ec + nt * 8;
            *(float2*)c0 = make_float2(acc[mt][nt][0], acc[mt][nt][1]);
            float* c1 = c0 + 8 * N;
            *(float2*)c1 = make_float2(acc[mt][nt][2], acc[mt][nt][3]);
        }
#undef LOAD_STAGE2
}

// ---------------------------------------------------------------------------
// Fused qk RMSNorm + RoPE -> bf16 hi/lo planes. Q scaled by 1/sqrt(HD).
// ---------------------------------------------------------------------------
__global__ void __launch_bounds__(256) normrope_kernel(
    const float* __restrict__ qkv,
    const float* __restrict__ nw_q, const float* __restrict__ nw_k,
    __nv_bfloat16* __restrict__ qh, __nv_bfloat16* __restrict__ ql,
    __nv_bfloat16* __restrict__ kh, __nv_bfloat16* __restrict__ kl)
{
    __shared__ float buf[HID];
    __shared__ float warpred[8];

    const int row = blockIdx.x;
    const int s = row & (S_ - 1);
    const int tid = threadIdx.x;

#pragma unroll
    for (int part = 0; part < 2; part++) {
        const float* src = qkv + (size_t)row * QKV_W + part * HID;
        const float* w = (part == 0) ? nw_q : nw_k;
        __nv_bfloat16* dh = (part == 0) ? qh : kh;
        __nv_bfloat16* dl = (part == 0) ? ql : kl;

        float ss = 0.0f;
#pragma unroll
        for (int u = 0; u < 8; u++) {
            int idx = tid + u * 256;
            float v = src[idx];
            buf[idx] = v;
            ss += v * v;
        }
#pragma unroll
        for (int o = 16; o; o >>= 1) ss += __shfl_xor_sync(0xffffffffu, ss, o);
        if ((tid & 31) == 0) warpred[tid >> 5] = ss;
        __syncthreads();
        float tot = 0.0f;
#pragma unroll
        for (int wi = 0; wi < 8; wi++) tot += warpred[wi];
        float rn = rsqrtf(tot * (1.0f / (float)HID) + EPS);
        if (part == 0) rn *= SCALE;

#pragma unroll
        for (int u = 0; u < 4; u++) {
            int p = tid + u * 256;
            int hh = p >> 6;
            int j = p & 63;
            int i1 = hh * HD + j;
            int i2 = i1 + HALF;
            float x1 = buf[i1] * rn * w[i1];
            float x2 = buf[i2] * rn * w[i2];
            float cs = g_cos[s * HALF + j];
            float sn = g_sin[s * HALF + j];
            float o1 = x1 * cs - x2 * sn;
            float o2 = x2 * cs + x1 * sn;
            __nv_bfloat16 h1 = __float2bfloat16(o1);
            __nv_bfloat16 h2 = __float2bfloat16(o2);
            size_t base = (size_t)row * HID;
            dh[base + i1] = h1;
            dh[base + i2] = h2;
            dl[base + i1] = __float2bfloat16(o1 - __bfloat162float(h1));
            dl[base + i2] = __float2bfloat16(o2 - __bfloat162float(h2));
        }
        __syncthreads();
    }
}

// ---------------------------------------------------------------------------
// V transpose + split: g_qkv v cols -> vt_hi/vt_lo [b][h][d][s]
// ---------------------------------------------------------------------------
__global__ void __launch_bounds__(256) vtrans_kernel(
    const float* __restrict__ qkv,
    __nv_bfloat16* __restrict__ vth, __nv_bfloat16* __restrict__ vtl)
{
    __shared__ float t[32][33];
    const int row0 = blockIdx.x * 32;
    const int col0 = blockIdx.y * 32;
    const int tx = threadIdx.x & 31;
    const int ty = threadIdx.x >> 5;
#pragma unroll
    for (int i = 0; i < 4; i++) {
        int r = ty + i * 8;
        t[r][tx] = qkv[(size_t)(row0 + r) * QKV_W + 2 * HID + col0 + tx];
    }
    __syncthreads();
    const int b = row0 >> 11;
    const int s0 = row0 & 2047;
#pragma unroll
    for (int i = 0; i < 4; i++) {
        int c = ty + i * 8;
        float v = t[tx][c];
        __nv_bfloat16 h = __float2bfloat16(v);
        size_t o = ((size_t)(b * 2048 + col0 + c)) * 2048 + s0 + tx;
        vth[o] = h;
        vtl[o] = __float2bfloat16(v - __bfloat162float(h));
    }
}

// ---------------------------------------------------------------------------
// Flash attention, bf16 mma.sync, 3-term split with hoisted fragment reuse.
// Block: 128 q rows x one (b,h). 8 warps (16 rows each). 2-stage KV pipeline.
// Output -> g_a_hi / g_a_lo planes (gemm2 A operand).
// ---------------------------------------------------------------------------
#define SQH 0
#define SQL 32768
#define SKH(s) (65536 + (s) * 65536)
#define SKL(s) (SKH(s) + 16384)
#define SVH(s) (SKH(s) + 32768)
#define SVL(s) (SKH(s) + 49152)
#define ATTN_SMEM (65536 + 2 * 65536)   // 196608

__global__ void __launch_bounds__(256, 1) attn_mma(
    const __nv_bfloat16* __restrict__ qh, const __nv_bfloat16* __restrict__ ql,
    const __nv_bfloat16* __restrict__ kh, const __nv_bfloat16* __restrict__ kl,
    const __nv_bfloat16* __restrict__ vth, const __nv_bfloat16* __restrict__ vtl,
    __nv_bfloat16* __restrict__ ohi, __nv_bfloat16* __restrict__ olo)
{
    extern __shared__ char smem[];
    const uint32_t sb = smem_u32(smem);
    const int tid = threadIdx.x;
    const int wid = tid >> 5, lid = tid & 31;
    const int lrow = lid & 15;
    const int lhi = (lid >> 4) * 16;
    const int bh = blockIdx.y;
    const int b = bh >> 4, h = bh & 15;
    const int qt = gridDim.x - 1 - blockIdx.x;
    const int q0 = qt * 128;
    const int nkb = qt * 2 + 2;
    const int wm = wid * 16;

    // ---- load Q (hi+lo) into smem ----
#pragma unroll
    for (int u = 0; u < 16; u++) {
        int c = tid + u * 256;
        int plane = c >> 11;
        int cc = c & 2047;
        int r = cc >> 4, ch = cc & 15;
        int p = ch >> 3, c8 = ch & 7;
        const __nv_bfloat16* src = (plane ? ql : qh) +
            ((size_t)(b * 2048 + q0 + r) * HID + h * HD + ch * 8);
        uint32_t dst = sb + (plane ? SQL : SQH) + p * 16384 + SWZ(r * 128 + c8 * 16);
        asm volatile("cp.async.cg.shared.global [%0], [%1], 16;"
                     :: "r"(dst), "l"(src) : "memory");
    }
    asm volatile("cp.async.commit_group;" ::: "memory");

#define LOAD_KV(s, kt) do {                                                    \
    int k0 = (kt) * 64;                                                        \
    _Pragma("unroll")                                                          \
    for (int u = 0; u < 16; u++) {                                             \
        int c = tid + u * 256;                                                 \
        if (c < 2048) {                                                        \
            int plane = c >> 10;                                               \
            int cc = c & 1023;                                                 \
            int r = cc >> 4, ch = cc & 15;                                     \
            int p = ch >> 3, c8 = ch & 7;                                      \
            const __nv_bfloat16* src = (plane ? kl : kh) +                     \
                ((size_t)(b * 2048 + k0 + r) * HID + h * HD + ch * 8);         \
            uint32_t dst = sb + (plane ? SKL(s) : SKH(s)) + p * 8192 +         \
                           SWZ(r * 128 + c8 * 16);                             \
            asm volatile("cp.async.cg.shared.global [%0], [%1], 16;"           \
                         :: "r"(dst), "l"(src) : "memory");                    \
        } else {                                                               \
            int plane = (c >> 10) & 1;                                         \
            int cc = c & 1023;                                                 \
            int d = cc >> 3, c8 = cc & 7;                                      \
            const __nv_bfloat16* src = (plane ? vtl : vth) +                   \
                ((size_t)(b * 2048 + h * HD + d) * 2048 + k0 + c8 * 8);        \
            uint32_t dst = sb + (plane ? SVL(s) : SVH(s)) +                    \
                           SWZ(d * 128 + c8 * 16);                             \
            asm volatile("cp.async.cg.shared.global [%0], [%1], 16;"           \
                         :: "r"(dst), "l"(src) : "memory");                    \
        }                                                                      \
    }                                                                          \
} while (0)

    LOAD_KV(0, 0);
    asm volatile("cp.async.commit_group;" ::: "memory");

    float accO[16][4];
#pragma unroll
    for (int nt = 0; nt < 16; nt++)
#pragma unroll
        for (int q = 0; q < 4; q++) accO[nt][q] = 0.0f;
    float m0v = -1e30f, m1v = -1e30f, l0v = 0.0f, l1v = 0.0f;

    const int grow0 = q0 + wm + (lid >> 2);
    const int grow1 = grow0 + 8;

    for (int kt = 0; kt < nkb; kt++) {
        __syncthreads();
        if (kt + 1 < nkb) LOAD_KV((kt + 1) & 1, kt + 1);
        asm volatile("cp.async.commit_group;" ::: "memory");
        asm volatile("cp.async.wait_group 1;" ::: "memory");
        __syncthreads();

        const int s = kt & 1;

        // ---- S = Qh*Kh + Ql*Kh + Qh*Kl  (Qh, Kh frags reused) ----
        float sa[8][4];
#pragma unroll
        for (int nt = 0; nt < 8; nt++)
#pragma unroll
            for (int q = 0; q < 4; q++) sa[nt][q] = 0.0f;

#pragma unroll
        for (int kk = 0; kk < 8; kk++) {
            int p = kk >> 2;
            int cb = (kk & 3) * 32 + lhi;
            int arow = wm + lrow;
            uint32_t aoff = p * 16384 + arow * 128 + (cb ^ ((arow & 7) * 16));
            uint32_t qhf[4], qlf[4];
            ldsm_x4(qhf, sb + SQH + aoff);
            ldsm_x4(qlf, sb + SQL + aoff);
#pragma unroll
            for (int np = 0; np < 4; np++) {
                int brow = np * 16 + lrow;
                uint32_t boff = p * 8192 + brow * 128 + (cb ^ ((brow & 7) * 16));
                uint32_t khf[4];
                ldsm_x4(khf, sb + SKH(s) + boff);
                mma_bf16(sa[np * 2 + 0], qhf, khf[0], khf[2]);
                mma_bf16(sa[np * 2 + 1], qhf, khf[1], khf[3]);
                mma_bf16(sa[np * 2 + 0], qlf, khf[0], khf[2]);
                mma_bf16(sa[np * 2 + 1], qlf, khf[1], khf[3]);
                uint32_t klf[4];
                ldsm_x4(klf, sb + SKL(s) + boff);
                mma_bf16(sa[np * 2 + 0], qhf, klf[0], klf[2]);
                mma_bf16(sa[np * 2 + 1], qhf, klf[1], klf[3]);
            }
        }

        // ---- causal mask ----
        if ((kt + 1) * 64 - 1 > q0 + wm) {
            const int colb = kt * 64 + (lid & 3) * 2;
#pragma unroll
            for (int nt = 0; nt < 8; nt++) {
                int col = colb + nt * 8;
                if (col > grow0)     sa[nt][0] = -1e30f;
                if (col + 1 > grow0) sa[nt][1] = -1e30f;
                if (col > grow1)     sa[nt][2] = -1e30f;
                if (col + 1 > grow1) sa[nt][3] = -1e30f;
            }
        }

        // ---- online softmax ----
        float mx0 = m0v, mx1 = m1v;
#pragma unroll
        for (int nt = 0; nt < 8; nt++) {
            mx0 = fmaxf(mx0, fmaxf(sa[nt][0], sa[nt][1]));
            mx1 = fmaxf(mx1, fmaxf(sa[nt][2], sa[nt][3]));
        }
        mx0 = fmaxf(mx0, __shfl_xor_sync(0xffffffffu, mx0, 1));
        mx0 = fmaxf(mx0, __shfl_xor_sync(0xffffffffu, mx0, 2));
        mx1 = fmaxf(mx1, __shfl_xor_sync(0xffffffffu, mx1, 1));
        mx1 = fmaxf(mx1, __shfl_xor_sync(0xffffffffu, mx1, 2));
        float alpha0 = __expf(m0v - mx0);
        float alpha1 = __expf(m1v - mx1);
        m0v = mx0; m1v = mx1;

        float ls0 = 0.0f, ls1 = 0.0f;
#pragma unroll
        for (int nt = 0; nt < 8; nt++) {
            sa[nt][0] = __expf(sa[nt][0] - mx0);
            sa[nt][1] = __expf(sa[nt][1] - mx0);
            sa[nt][2] = __expf(sa[nt][2] - mx1);
            sa[nt][3] = __expf(sa[nt][3] - mx1);
            ls0 += sa[nt][0] + sa[nt][1];
            ls1 += sa[nt][2] + sa[nt][3];
        }
        ls0 += __shfl_xor_sync(0xffffffffu, ls0, 1);
        ls0 += __shfl_xor_sync(0xffffffffu, ls0, 2);
        ls1 += __shfl_xor_sync(0xffffffffu, ls1, 1);
        ls1 += __shfl_xor_sync(0xffffffffu, ls1, 2);
        l0v = l0v * alpha0 + ls0;
        l1v = l1v * alpha1 + ls1;

#pragma unroll
        for (int nt = 0; nt < 16; nt++) {
            accO[nt][0] *= alpha0; accO[nt][1] *= alpha0;
            accO[nt][2] *= alpha1; accO[nt][3] *= alpha1;
        }

        // ---- P split into bf16 hi/lo A-fragments ----
        uint32_t phA[8], phB[8], plA[8], plB[8];
#pragma unroll
        for (int nt = 0; nt < 8; nt++) {
            float h0 = __bfloat162float(__float2bfloat16(sa[nt][0]));
            float h1 = __bfloat162float(__float2bfloat16(sa[nt][1]));
            float h2 = __bfloat162float(__float2bfloat16(sa[nt][2]));
            float h3 = __bfloat162float(__float2bfloat16(sa[nt][3]));
            phA[nt] = pack_bf16x2(h0, h1);
            phB[nt] = pack_bf16x2(h2, h3);
            plA[nt] = pack_bf16x2(sa[nt][0] - h0, sa[nt][1] - h1);
            plB[nt] = pack_bf16x2(sa[nt][2] - h2, sa[nt][3] - h3);
        }

        // ---- O += Ph*Vh + Pl*Vh + Ph*Vl  (Vh frags reused) ----
#pragma unroll
        for (int ki = 0; ki < 4; ki++) {
            uint32_t aH[4] = {phA[2 * ki], phB[2 * ki], phA[2 * ki + 1], phB[2 * ki + 1]};
            uint32_t aL[4] = {plA[2 * ki], plB[2 * ki], plA[2 * ki + 1], plB[2 * ki + 1]};
            int cb = ki * 32 + lhi;
#pragma unroll
            for (int np = 0; np < 8; np++) {
                int brow = np * 16 + lrow;
                uint32_t boff = brow * 128 + (cb ^ ((brow & 7) * 16));
                uint32_t vhf[4];
                ldsm_x4(vhf, sb + SVH(s) + boff);
                mma_bf16(accO[np * 2 + 0], aH, vhf[0], vhf[2]);
                mma_bf16(accO[np * 2 + 1], aH, vhf[1], vhf[3]);
                mma_bf16(accO[np * 2 + 0], aL, vhf[0], vhf[2]);
                mma_bf16(accO[np * 2 + 1], aL, vhf[1], vhf[3]);
                uint32_t vlf[4];
                ldsm_x4(vlf, sb + SVL(s) + boff);
                mma_bf16(accO[np * 2 + 0], aH, vlf[0], vlf[2]);
                mma_bf16(accO[np * 2 + 1], aH, vlf[1], vlf[3]);
            }
        }
    }

    // ---- epilogue: O/l -> hi/lo planes ----
    float inv0 = 1.0f / l0v, inv1 = 1.0f / l1v;
#pragma unroll
    for (int nt = 0; nt < 16; nt++) {
        int col = h * HD + nt * 8 + (lid & 3) * 2;
        float o0 = accO[nt][0] * inv0, o1 = accO[nt][1] * inv0;
        float o2 = accO[nt][2] * inv1, o3 = accO[nt][3] * inv1;
        float h0 = __bfloat162float(__float2bfloat16(o0));
        float h1 = __bfloat162float(__float2bfloat16(o1));
        float h2 = __bfloat162float(__float2bfloat16(o2));
        float h3 = __bfloat162float(__float2bfloat16(o3));
        size_t r0 = (size_t)(b * 2048 + grow0) * HID + col;
        size_t r1 = (size_t)(b * 2048 + grow1) * HID + col;
        *(uint32_t*)(ohi + r0) = pack_bf16x2(h0, h1);
        *(uint32_t*)(ohi + r1) = pack_bf16x2(h2, h3);
        *(uint32_t*)(olo + r0) = pack_bf16x2(o0 - h0, o1 - h1);
        *(uint32_t*)(olo + r1) = pack_bf16x2(o2 - h2, o3 - h3);
    }
#undef LOAD_KV
}

// ---------------------------------------------------------------------------
// launch
// ---------------------------------------------------------------------------
extern "C" void kernel_launch(void* const* d_in, const int* in_sizes, int n_in,
                              void* d_out, int out_size)
{
    const float* x     = (const float*)d_in[0];
    const float* w_in  = (const float*)d_in[1];
    const float* w_out = (const float*)d_in[2];
    const float* qnw   = (const float*)d_in[3];
    const float* knw   = (const float*)d_in[4];
    float* out = (float*)d_out;

    float* qkv;  cudaGetSymbolAddress((void**)&qkv,  g_qkv);
    __nv_bfloat16 *ah, *al, *bhp, *blp, *qh, *ql, *kh, *kl, *vth, *vtl;
    cudaGetSymbolAddress((void**)&ah, g_a_hi);
    cudaGetSymbolAddress((void**)&al, g_a_lo);
    cudaGetSymbolAddress((void**)&bhp, g_b_hi);
    cudaGetSymbolAddress((void**)&blp, g_b_lo);
    cudaGetSymbolAddress((void**)&qh, g_q_hi);
    cudaGetSymbolAddress((void**)&ql, g_q_lo);
    cudaGetSymbolAddress((void**)&kh, g_k_hi);
    cudaGetSymbolAddress((void**)&kl, g_k_lo);
    cudaGetSymbolAddress((void**)&vth, g_vt_hi);
    cudaGetSymbolAddress((void**)&vtl, g_vt_lo);

    cudaFuncSetAttribute(gemm_mma2, cudaFuncAttributeMaxDynamicSharedMemorySize, GEMM_SMEM);
    cudaFuncSetAttribute(attn_mma, cudaFuncAttributeMaxDynamicSharedMemorySize, ATTN_SMEM);

    // 1. split x -> a planes, w_in -> b planes
    split2_kernel<<<(ROWS * HID / 4 + 255) / 256, 256>>>(x, ah, al, ROWS * HID / 4);
    split2_kernel<<<(QKV_W * HID / 4 + 255) / 256, 256>>>(w_in, bhp, blp, QKV_W * HID / 4);

    // 2. QKV = x @ w_in^T
    gemm_mma2<<<(ROWS / BM) * (QKV_W / BN), 256, GEMM_SMEM>>>(ah, al, bhp, blp, qkv, ROWS, QKV_W);

    // 3. tables + norm/rope -> bf16 planes; V transpose/split
    rope_table_kernel<<<(S_ * HALF + 255) / 256, 256>>>();
    normrope_kernel<<<ROWS, 256>>>(qkv, qnw, knw, qh, ql, kh, kl);
    vtrans_kernel<<<dim3(ROWS / 32, HID / 32), 256>>>(qkv, vth, vtl);

    // 4. attention -> a planes (gemm2 A operand)
    attn_mma<<<dim3(S_ / 128, B_ * NH), 256, ATTN_SMEM>>>(qh, ql, kh, kl, vth, vtl, ah, al);

    // 5. w_out -> b planes; out = O @ w_out^T
    split2_kernel<<<(HID * HID / 4 + 255) / 256, 256>>>(w_out, bhp, blp, HID * HID / 4);
    gemm_mma2<<<(ROWS / BM) * (HID / BN), 256, GEMM_SMEM>>>(ah, al, bhp, blp, out, ROWS, HID);
}

// round 7
// speedup vs baseline: 1.6052x; 1.6052x over previous
#include <cuda_runtime.h>
#include <cuda_bf16.h>
#include <cstdint>
#include <math.h>

// Problem constants
#define B_  2
#define S_  2048
#define HID 2048
#define NH  16
#define HD  128
#define HALF 64
#define ROWS (B_ * S_)            // 4096
#define QKV_W (3 * HID)           // 6144
#define EPS 1e-5f
#define SCALE 0.08838834764831845f   // 1/sqrt(128)

// Scratch (device-global; no runtime allocation allowed)
__device__ float g_qkv[(size_t)ROWS * QKV_W];            // gemm1 out (fp32)
__device__ float g_cos[S_ * HALF];
__device__ float g_sin[S_ * HALF];
__device__ __nv_bfloat16 g_a_hi[(size_t)ROWS * HID];     // gemm A hi plane (x; then O)
__device__ __nv_bfloat16 g_a_lo[(size_t)ROWS * HID];
__device__ __nv_bfloat16 g_b_hi[(size_t)QKV_W * HID];    // gemm B hi plane (w_in; then w_out)
__device__ __nv_bfloat16 g_b_lo[(size_t)QKV_W * HID];
__device__ __nv_bfloat16 g_q_hi[(size_t)ROWS * HID];
__device__ __nv_bfloat16 g_q_lo[(size_t)ROWS * HID];
__device__ __nv_bfloat16 g_k_hi[(size_t)ROWS * HID];
__device__ __nv_bfloat16 g_k_lo[(size_t)ROWS * HID];
__device__ __nv_bfloat16 g_vt_hi[(size_t)ROWS * HID];    // [b][h][d][s]
__device__ __nv_bfloat16 g_vt_lo[(size_t)ROWS * HID];

__device__ __forceinline__ uint32_t smem_u32(const void* p) {
    uint32_t a;
    asm("{ .reg .u64 t; cvta.to.shared.u64 t, %1; cvt.u32.u64 %0, t; }" : "=r"(a) : "l"(p));
    return a;
}
#define SWZ(x) ((x) ^ (((x) >> 3) & 0x70))

__device__ __forceinline__ void ldsm_x4(uint32_t* r, uint32_t addr) {
    asm volatile("ldmatrix.sync.aligned.m8n8.x4.shared.b16 {%0,%1,%2,%3}, [%4];"
                 : "=r"(r[0]), "=r"(r[1]), "=r"(r[2]), "=r"(r[3]) : "r"(addr));
}
__device__ __forceinline__ void mma_bf16(float* c, const uint32_t* a,
                                         uint32_t b0, uint32_t b1) {
    asm volatile(
        "mma.sync.aligned.m16n8k16.row.col.f32.bf16.bf16.f32 "
        "{%0,%1,%2,%3}, {%4,%5,%6,%7}, {%8,%9}, {%0,%1,%2,%3};"
        : "+f"(c[0]), "+f"(c[1]), "+f"(c[2]), "+f"(c[3])
        : "r"(a[0]), "r"(a[1]), "r"(a[2]), "r"(a[3]), "r"(b0), "r"(b1));
}
__device__ __forceinline__ uint32_t pack_bf16x2(float lo, float hi) {
    uint32_t r;
    asm("cvt.rn.bf16x2.f32 %0, %1, %2;" : "=r"(r) : "f"(hi), "f"(lo));
    return r;
}

// ---------------------------------------------------------------------------
// RoPE table
// ---------------------------------------------------------------------------
__global__ void rope_table_kernel() {
    int idx = blockIdx.x * blockDim.x + threadIdx.x;
    if (idx >= S_ * HALF) return;
    int s = idx >> 6;
    int j = idx & 63;
    float freq = powf(10000.0f, -(float)j * (1.0f / 64.0f));
    float sn, cs;
    sincosf((float)s * freq, &sn, &cs);
    g_cos[idx] = cs;
    g_sin[idx] = sn;
}

// ---------------------------------------------------------------------------
// hi/lo split: fp32 -> two bf16 planes (flat)
// ---------------------------------------------------------------------------
__global__ void __launch_bounds__(256) split2_kernel(
    const float* __restrict__ src, __nv_bfloat16* __restrict__ hi,
    __nv_bfloat16* __restrict__ lo, int n4)
{
    int i = blockIdx.x * blockDim.x + threadIdx.x;
    if (i >= n4) return;
    float4 v = ((const float4*)src)[i];
    float vv[4] = {v.x, v.y, v.z, v.w};
    uint64_t hp = 0, lp = 0;
#pragma unroll
    for (int q = 0; q < 4; q++) {
        __nv_bfloat16 h = __float2bfloat16(vv[q]);
        __nv_bfloat16 l = __float2bfloat16(vv[q] - __bfloat162float(h));
        hp |= (uint64_t)__bfloat16_as_ushort(h) << (q * 16);
        lp |= (uint64_t)__bfloat16_as_ushort(l) << (q * 16);
    }
    *(uint64_t*)(hi + (size_t)i * 4) = hp;
    *(uint64_t*)(lo + (size_t)i * 4) = lp;
}

// ---------------------------------------------------------------------------
// 3-term split GEMM: C[M,N] = Ah*Bh^T + Al*Bh^T + Ah*Bl^T
// R4 launch shape (512 thr, 16 warps 4x4, warp tile 32x64) + R5 algorithm
// (separate hi/lo planes over K=2048, hoisted Ah/Bh fragment reuse).
// BK=64, 2 stages x 96KB.
// ---------------------------------------------------------------------------
#define BM 128
#define BN 256
#define BK 64
#define NK2 (HID / BK)            // 32
#define SAH 0
#define SAL 16384
#define SBH 32768
#define SBL 65536
#define STG2 98304
#define GEMM_SMEM (2 * STG2)      // 196608

__global__ void __launch_bounds__(512, 1) gemm_mma3(
    const __nv_bfloat16* __restrict__ Ah, const __nv_bfloat16* __restrict__ Al,
    const __nv_bfloat16* __restrict__ Bh, const __nv_bfloat16* __restrict__ Bl,
    float* __restrict__ C, int M, int N)
{
    extern __shared__ char smem[];
    const uint32_t sb = smem_u32(smem);
    const int tid = threadIdx.x;
    const int wid = tid >> 5, lid = tid & 31;
    const int tiles_m = M / BM;
    const int m0 = (blockIdx.x % tiles_m) * BM;
    const int n0 = (blockIdx.x / tiles_m) * BN;
    const int wm = (wid & 3) * 32;     // R4 warp geometry
    const int wn = (wid >> 2) * 64;
    const int lrow = lid & 15;
    const int lhi = (lid >> 4) * 16;

#define LOAD_STAGE3(st, kt) do {                                               \
    uint32_t sbase = sb + (st) * STG2;                                         \
    _Pragma("unroll")                                                          \
    for (int u = 0; u < 12; u++) {                                             \
        int c = tid + u * 512;                                                 \
        const __nv_bfloat16* gp;                                               \
        uint32_t dst;                                                          \
        if (c < 2048) {                                                        \
            int plane = c >> 10;                                               \
            int cc = c & 1023;                                                 \
            int r = cc >> 3, c16 = cc & 7;                                     \
            gp = (plane ? Al : Ah) + (size_t)(m0 + r) * HID + (kt) * BK + c16 * 8; \
            dst = sbase + (plane ? SAL : SAH) + SWZ(r * 128 + c16 * 16);       \
        } else {                                                               \
            int cc = c - 2048;                                                 \
            int plane = cc >> 11;                                              \
            int c2 = cc & 2047;                                                \
            int r = c2 >> 3, c16 = c2 & 7;                                     \
            gp = (plane ? Bl : Bh) + (size_t)(n0 + r) * HID + (kt) * BK + c16 * 8; \
            dst = sbase + (plane ? SBL : SBH) + SWZ(r * 128 + c16 * 16);       \
        }                                                                      \
        asm volatile("cp.async.cg.shared.global [%0], [%1], 16;"               \
                     :: "r"(dst), "l"(gp) : "memory");                         \
    }                                                                          \
} while (0)

    LOAD_STAGE3(0, 0);
    asm volatile("cp.async.commit_group;" ::: "memory");

    float acc[2][8][4];
#pragma unroll
    for (int mt = 0; mt < 2; mt++)
#pragma unroll
        for (int nt = 0; nt < 8; nt++)
#pragma unroll
            for (int q = 0; q < 4; q++) acc[mt][nt][q] = 0.0f;

    for (int kt = 0; kt < NK2; kt++) {
        if (kt + 1 < NK2) LOAD_STAGE3((kt + 1) & 1, kt + 1);
        asm volatile("cp.async.commit_group;" ::: "memory");
        asm volatile("cp.async.wait_group 1;" ::: "memory");
        __syncthreads();

        const uint32_t sbase = sb + (kt & 1) * STG2;

#pragma unroll
        for (int ks = 0; ks < 4; ks++) {
            const int cb = ks * 32 + lhi;
            uint32_t ahf[2][4], alf[2][4];
#pragma unroll
            for (int mt = 0; mt < 2; mt++) {
                int row = wm + mt * 16 + lrow;
                uint32_t off = row * 128 + (cb ^ ((row & 7) * 16));
                ldsm_x4(ahf[mt], sbase + SAH + off);
                ldsm_x4(alf[mt], sbase + SAL + off);
            }
#pragma unroll
            for (int np = 0; np < 4; np++) {
                int brow = wn + np * 16 + lrow;
                uint32_t boff = brow * 128 + (cb ^ ((brow & 7) * 16));
                uint32_t bh4[4];
                ldsm_x4(bh4, sbase + SBH + boff);
#pragma unroll
                for (int mt = 0; mt < 2; mt++) {
                    mma_bf16(acc[mt][np * 2 + 0], ahf[mt], bh4[0], bh4[2]);
                    mma_bf16(acc[mt][np * 2 + 1], ahf[mt], bh4[1], bh4[3]);
                    mma_bf16(acc[mt][np * 2 + 0], alf[mt], bh4[0], bh4[2]);
                    mma_bf16(acc[mt][np * 2 + 1], alf[mt], bh4[1], bh4[3]);
                }
                uint32_t bl4[4];
                ldsm_x4(bl4, sbase + SBL + boff);
#pragma unroll
                for (int mt = 0; mt < 2; mt++) {
                    mma_bf16(acc[mt][np * 2 + 0], ahf[mt], bl4[0], bl4[2]);
                    mma_bf16(acc[mt][np * 2 + 1], ahf[mt], bl4[1], bl4[3]);
                }
            }
        }
        __syncthreads();
    }

    const int er = m0 + wm + (lid >> 2);
    const int ec = n0 + wn + (lid & 3) * 2;
#pragma unroll
    for (int mt = 0; mt < 2; mt++)
#pragma unroll
        for (int nt = 0; nt < 8; nt++) {
            float* c0 = C + (size_t)(er + mt * 16) * N + ec + nt * 8;
            *(float2*)c0 = make_float2(acc[mt][nt][0], acc[mt][nt][1]);
            float* c1 = c0 + 8 * N;
            *(float2*)c1 = make_float2(acc[mt][nt][2], acc[mt][nt][3]);
        }
#undef LOAD_STAGE3
}

// ---------------------------------------------------------------------------
// Fused qk RMSNorm + RoPE -> bf16 hi/lo planes. Q scaled by 1/sqrt(HD).
// ---------------------------------------------------------------------------
__global__ void __launch_bounds__(256) normrope_kernel(
    const float* __restrict__ qkv,
    const float* __restrict__ nw_q, const float* __restrict__ nw_k,
    __nv_bfloat16* __restrict__ qh, __nv_bfloat16* __restrict__ ql,
    __nv_bfloat16* __restrict__ kh, __nv_bfloat16* __restrict__ kl)
{
    __shared__ float buf[HID];
    __shared__ float warpred[8];

    const int row = blockIdx.x;
    const int s = row & (S_ - 1);
    const int tid = threadIdx.x;

#pragma unroll
    for (int part = 0; part < 2; part++) {
        const float* src = qkv + (size_t)row * QKV_W + part * HID;
        const float* w = (part == 0) ? nw_q : nw_k;
        __nv_bfloat16* dh = (part == 0) ? qh : kh;
        __nv_bfloat16* dl = (part == 0) ? ql : kl;

        float ss = 0.0f;
#pragma unroll
        for (int u = 0; u < 8; u++) {
            int idx = tid + u * 256;
            float v = src[idx];
            buf[idx] = v;
            ss += v * v;
        }
#pragma unroll
        for (int o = 16; o; o >>= 1) ss += __shfl_xor_sync(0xffffffffu, ss, o);
        if ((tid & 31) == 0) warpred[tid >> 5] = ss;
        __syncthreads();
        float tot = 0.0f;
#pragma unroll
        for (int wi = 0; wi < 8; wi++) tot += warpred[wi];
        float rn = rsqrtf(tot * (1.0f / (float)HID) + EPS);
        if (part == 0) rn *= SCALE;

#pragma unroll
        for (int u = 0; u < 4; u++) {
            int p = tid + u * 256;
            int hh = p >> 6;
            int j = p & 63;
            int i1 = hh * HD + j;
            int i2 = i1 + HALF;
            float x1 = buf[i1] * rn * w[i1];
            float x2 = buf[i2] * rn * w[i2];
            float cs = g_cos[s * HALF + j];
            float sn = g_sin[s * HALF + j];
            float o1 = x1 * cs - x2 * sn;
            float o2 = x2 * cs + x1 * sn;
            __nv_bfloat16 h1 = __float2bfloat16(o1);
            __nv_bfloat16 h2 = __float2bfloat16(o2);
            size_t base = (size_t)row * HID;
            dh[base + i1] = h1;
            dh[base + i2] = h2;
            dl[base + i1] = __float2bfloat16(o1 - __bfloat162float(h1));
            dl[base + i2] = __float2bfloat16(o2 - __bfloat162float(h2));
        }
        __syncthreads();
    }
}

// ---------------------------------------------------------------------------
// V transpose + split: g_qkv v cols -> vt_hi/vt_lo [b][h][d][s]
// ---------------------------------------------------------------------------
__global__ void __launch_bounds__(256) vtrans_kernel(
    const float* __restrict__ qkv,
    __nv_bfloat16* __restrict__ vth, __nv_bfloat16* __restrict__ vtl)
{
    __shared__ float t[32][33];
    const int row0 = blockIdx.x * 32;
    const int col0 = blockIdx.y * 32;
    const int tx = threadIdx.x & 31;
    const int ty = threadIdx.x >> 5;
#pragma unroll
    for (int i = 0; i < 4; i++) {
        int r = ty + i * 8;
        t[r][tx] = qkv[(size_t)(row0 + r) * QKV_W + 2 * HID + col0 + tx];
    }
    __syncthreads();
    const int b = row0 >> 11;
    const int s0 = row0 & 2047;
#pragma unroll
    for (int i = 0; i < 4; i++) {
        int c = ty + i * 8;
        float v = t[tx][c];
        __nv_bfloat16 h = __float2bfloat16(v);
        size_t o = ((size_t)(b * 2048 + col0 + c)) * 2048 + s0 + tx;
        vth[o] = h;
        vtl[o] = __float2bfloat16(v - __bfloat162float(h));
    }
}

// ---------------------------------------------------------------------------
// Flash attention, bf16 mma.sync, 3-term split with hoisted fragment reuse.
// Block: 128 q rows x one (b,h). 8 warps. 2-stage KV pipeline.
// Output -> g_a_hi / g_a_lo planes (gemm2 A operand).
// ---------------------------------------------------------------------------
#define SQH 0
#define SQL 32768
#define SKH(s) (65536 + (s) * 65536)
#define SKL(s) (SKH(s) + 16384)
#define SVH(s) (SKH(s) + 32768)
#define SVL(s) (SKH(s) + 49152)
#define ATTN_SMEM (65536 + 2 * 65536)   // 196608

__global__ void __launch_bounds__(256, 1) attn_mma(
    const __nv_bfloat16* __restrict__ qh, const __nv_bfloat16* __restrict__ ql,
    const __nv_bfloat16* __restrict__ kh, const __nv_bfloat16* __restrict__ kl,
    const __nv_bfloat16* __restrict__ vth, const __nv_bfloat16* __restrict__ vtl,
    __nv_bfloat16* __restrict__ ohi, __nv_bfloat16* __restrict__ olo)
{
    extern __shared__ char smem[];
    const uint32_t sb = smem_u32(smem);
    const int tid = threadIdx.x;
    const int wid = tid >> 5, lid = tid & 31;
    const int lrow = lid & 15;
    const int lhi = (lid >> 4) * 16;
    const int bh = blockIdx.y;
    const int b = bh >> 4, h = bh & 15;
    const int qt = gridDim.x - 1 - blockIdx.x;
    const int q0 = qt * 128;
    const int nkb = qt * 2 + 2;
    const int wm = wid * 16;

    // ---- load Q (hi+lo) into smem ----
#pragma unroll
    for (int u = 0; u < 16; u++) {
        int c = tid + u * 256;
        int plane = c >> 11;
        int cc = c & 2047;
        int r = cc >> 4, ch = cc & 15;
        int p = ch >> 3, c8 = ch & 7;
        const __nv_bfloat16* src = (plane ? ql : qh) +
            ((size_t)(b * 2048 + q0 + r) * HID + h * HD + ch * 8);
        uint32_t dst = sb + (plane ? SQL : SQH) + p * 16384 + SWZ(r * 128 + c8 * 16);
        asm volatile("cp.async.cg.shared.global [%0], [%1], 16;"
                     :: "r"(dst), "l"(src) : "memory");
    }
    asm volatile("cp.async.commit_group;" ::: "memory");

#define LOAD_KV(s, kt) do {                                                    \
    int k0 = (kt) * 64;                                                        \
    _Pragma("unroll")                                                          \
    for (int u = 0; u < 16; u++) {                                             \
        int c = tid + u * 256;                                                 \
        if (c < 2048) {                                                        \
            int plane = c >> 10;                                               \
            int cc = c & 1023;                                                 \
            int r = cc >> 4, ch = cc & 15;                                     \
            int p = ch >> 3, c8 = ch & 7;                                      \
            const __nv_bfloat16* src = (plane ? kl : kh) +                     \
                ((size_t)(b * 2048 + k0 + r) * HID + h * HD + ch * 8);         \
            uint32_t dst = sb + (plane ? SKL(s) : SKH(s)) + p * 8192 +         \
                           SWZ(r * 128 + c8 * 16);                             \
            asm volatile("cp.async.cg.shared.global [%0], [%1], 16;"           \
                         :: "r"(dst), "l"(src) : "memory");                    \
        } else {                                                               \
            int plane = (c >> 10) & 1;                                         \
            int cc = c & 1023;                                                 \
            int d = cc >> 3, c8 = cc & 7;                                      \
            const __nv_bfloat16* src = (plane ? vtl : vth) +                   \
                ((size_t)(b * 2048 + h * HD + d) * 2048 + k0 + c8 * 8);        \
            uint32_t dst = sb + (plane ? SVL(s) : SVH(s)) +                    \
                           SWZ(d * 128 + c8 * 16);                             \
            asm volatile("cp.async.cg.shared.global [%0], [%1], 16;"           \
                         :: "r"(dst), "l"(src) : "memory");                    \
        }                                                                      \
    }                                                                          \
} while (0)

    LOAD_KV(0, 0);
    asm volatile("cp.async.commit_group;" ::: "memory");

    float accO[16][4];
#pragma unroll
    for (int nt = 0; nt < 16; nt++)
#pragma unroll
        for (int q = 0; q < 4; q++) accO[nt][q] = 0.0f;
    float m0v = -1e30f, m1v = -1e30f, l0v = 0.0f, l1v = 0.0f;

    const int grow0 = q0 + wm + (lid >> 2);
    const int grow1 = grow0 + 8;

    for (int kt = 0; kt < nkb; kt++) {
        __syncthreads();
        if (kt + 1 < nkb) LOAD_KV((kt + 1) & 1, kt + 1);
        asm volatile("cp.async.commit_group;" ::: "memory");
        asm volatile("cp.async.wait_group 1;" ::: "memory");
        __syncthreads();

        const int s = kt & 1;

        // ---- S = Qh*Kh + Ql*Kh + Qh*Kl  (Qh, Kh frags reused) ----
        float sa[8][4];
#pragma unroll
        for (int nt = 0; nt < 8; nt++)
#pragma unroll
            for (int q = 0; q < 4; q++) sa[nt][q] = 0.0f;

#pragma unroll
        for (int kk = 0; kk < 8; kk++) {
            int p = kk >> 2;
            int cb = (kk & 3) * 32 + lhi;
            int arow = wm + lrow;
            uint32_t aoff = p * 16384 + arow * 128 + (cb ^ ((arow & 7) * 16));
            uint32_t qhf[4], qlf[4];
            ldsm_x4(qhf, sb + SQH + aoff);
            ldsm_x4(qlf, sb + SQL + aoff);
#pragma unroll
            for (int np = 0; np < 4; np++) {
                int brow = np * 16 + lrow;
                uint32_t boff = p * 8192 + brow * 128 + (cb ^ ((brow & 7) * 16));
                uint32_t khf[4];
                ldsm_x4(khf, sb + SKH(s) + boff);
                mma_bf16(sa[np * 2 + 0], qhf, khf[0], khf[2]);
                mma_bf16(sa[np * 2 + 1], qhf, khf[1], khf[3]);
                mma_bf16(sa[np * 2 + 0], qlf, khf[0], khf[2]);
                mma_bf16(sa[np * 2 + 1], qlf, khf[1], khf[3]);
                uint32_t klf[4];
                ldsm_x4(klf, sb + SKL(s) + boff);
                mma_bf16(sa[np * 2 + 0], qhf, klf[0], klf[2]);
                mma_bf16(sa[np * 2 + 1], qhf, klf[1], klf[3]);
            }
        }

        // ---- causal mask ----
        if ((kt + 1) * 64 - 1 > q0 + wm) {
            const int colb = kt * 64 + (lid & 3) * 2;
#pragma unroll
            for (int nt = 0; nt < 8; nt++) {
                int col = colb + nt * 8;
                if (col > grow0)     sa[nt][0] = -1e30f;
                if (col + 1 > grow0) sa[nt][1] = -1e30f;
                if (col > grow1)     sa[nt][2] = -1e30f;
                if (col + 1 > grow1) sa[nt][3] = -1e30f;
            }
        }

        // ---- online softmax ----
        float mx0 = m0v, mx1 = m1v;
#pragma unroll
        for (int nt = 0; nt < 8; nt++) {
            mx0 = fmaxf(mx0, fmaxf(sa[nt][0], sa[nt][1]));
            mx1 = fmaxf(mx1, fmaxf(sa[nt][2], sa[nt][3]));
        }
        mx0 = fmaxf(mx0, __shfl_xor_sync(0xffffffffu, mx0, 1));
        mx0 = fmaxf(mx0, __shfl_xor_sync(0xffffffffu, mx0, 2));
        mx1 = fmaxf(mx1, __shfl_xor_sync(0xffffffffu, mx1, 1));
        mx1 = fmaxf(mx1, __shfl_xor_sync(0xffffffffu, mx1, 2));
        float alpha0 = __expf(m0v - mx0);
        float alpha1 = __expf(m1v - mx1);
        m0v = mx0; m1v = mx1;

        float ls0 = 0.0f, ls1 = 0.0f;
#pragma unroll
        for (int nt = 0; nt < 8; nt++) {
            sa[nt][0] = __expf(sa[nt][0] - mx0);
            sa[nt][1] = __expf(sa[nt][1] - mx0);
            sa[nt][2] = __expf(sa[nt][2] - mx1);
            sa[nt][3] = __expf(sa[nt][3] - mx1);
            ls0 += sa[nt][0] + sa[nt][1];
            ls1 += sa[nt][2] + sa[nt][3];
        }
        ls0 += __shfl_xor_sync(0xffffffffu, ls0, 1);
        ls0 += __shfl_xor_sync(0xffffffffu, ls0, 2);
        ls1 += __shfl_xor_sync(0xffffffffu, ls1, 1);
        ls1 += __shfl_xor_sync(0xffffffffu, ls1, 2);
        l0v = l0v * alpha0 + ls0;
        l1v = l1v * alpha1 + ls1;

#pragma unroll
        for (int nt = 0; nt < 16; nt++) {
            accO[nt][0] *= alpha0; accO[nt][1] *= alpha0;
            accO[nt][2] *= alpha1; accO[nt][3] *= alpha1;
        }

        // ---- P split into bf16 hi/lo A-fragments ----
        uint32_t phA[8], phB[8], plA[8], plB[8];
#pragma unroll
        for (int nt = 0; nt < 8; nt++) {
            float h0 = __bfloat162float(__float2bfloat16(sa[nt][0]));
            float h1 = __bfloat162float(__float2bfloat16(sa[nt][1]));
            float h2 = __bfloat162float(__float2bfloat16(sa[nt][2]));
            float h3 = __bfloat162float(__float2bfloat16(sa[nt][3]));
            phA[nt] = pack_bf16x2(h0, h1);
            phB[nt] = pack_bf16x2(h2, h3);
            plA[nt] = pack_bf16x2(sa[nt][0] - h0, sa[nt][1] - h1);
            plB[nt] = pack_bf16x2(sa[nt][2] - h2, sa[nt][3] - h3);
        }

        // ---- O += Ph*Vh + Pl*Vh + Ph*Vl  (Vh frags reused) ----
#pragma unroll
        for (int ki = 0; ki < 4; ki++) {
            uint32_t aH[4] = {phA[2 * ki], phB[2 * ki], phA[2 * ki + 1], phB[2 * ki + 1]};
            uint32_t aL[4] = {plA[2 * ki], plB[2 * ki], plA[2 * ki + 1], plB[2 * ki + 1]};
            int cb = ki * 32 + lhi;
#pragma unroll
            for (int np = 0; np < 8; np++) {
                int brow = np * 16 + lrow;
                uint32_t boff = brow * 128 + (cb ^ ((brow & 7) * 16));
                uint32_t vhf[4];
                ldsm_x4(vhf, sb + SVH(s) + boff);
                mma_bf16(accO[np * 2 + 0], aH, vhf[0], vhf[2]);
                mma_bf16(accO[np * 2 + 1], aH, vhf[1], vhf[3]);
                mma_bf16(accO[np * 2 + 0], aL, vhf[0], vhf[2]);
                mma_bf16(accO[np * 2 + 1], aL, vhf[1], vhf[3]);
                uint32_t vlf[4];
                ldsm_x4(vlf, sb + SVL(s) + boff);
                mma_bf16(accO[np * 2 + 0], aH, vlf[0], vlf[2]);
                mma_bf16(accO[np * 2 + 1], aH, vlf[1], vlf[3]);
            }
        }
    }

    // ---- epilogue: O/l -> hi/lo planes ----
    float inv0 = 1.0f / l0v, inv1 = 1.0f / l1v;
#pragma unroll
    for (int nt = 0; nt < 16; nt++) {
        int col = h * HD + nt * 8 + (lid & 3) * 2;
        float o0 = accO[nt][0] * inv0, o1 = accO[nt][1] * inv0;
        float o2 = accO[nt][2] * inv1, o3 = accO[nt][3] * inv1;
        float h0 = __bfloat162float(__float2bfloat16(o0));
        float h1 = __bfloat162float(__float2bfloat16(o1));
        float h2 = __bfloat162float(__float2bfloat16(o2));
        float h3 = __bfloat162float(__float2bfloat16(o3));
        size_t r0 = (size_t)(b * 2048 + grow0) * HID + col;
        size_t r1 = (size_t)(b * 2048 + grow1) * HID + col;
        *(uint32_t*)(ohi + r0) = pack_bf16x2(h0, h1);
        *(uint32_t*)(ohi + r1) = pack_bf16x2(h2, h3);
        *(uint32_t*)(olo + r0) = pack_bf16x2(o0 - h0, o1 - h1);
        *(uint32_t*)(olo + r1) = pack_bf16x2(o2 - h2, o3 - h3);
    }
#undef LOAD_KV
}

// ---------------------------------------------------------------------------
// launch
// ---------------------------------------------------------------------------
extern "C" void kernel_launch(void* const* d_in, const int* in_sizes, int n_in,
                              void* d_out, int out_size)
{
    const float* x     = (const float*)d_in[0];
    const float* w_in  = (const float*)d_in[1];
    const float* w_out = (const float*)d_in[2];
    const float* qnw   = (const float*)d_in[3];
    const float* knw   = (const float*)d_in[4];
    float* out = (float*)d_out;

    float* qkv;  cudaGetSymbolAddress((void**)&qkv,  g_qkv);
    __nv_bfloat16 *ah, *al, *bhp, *blp, *qh, *ql, *kh, *kl, *vth, *vtl;
    cudaGetSymbolAddress((void**)&ah, g_a_hi);
    cudaGetSymbolAddress((void**)&al, g_a_lo);
    cudaGetSymbolAddress((void**)&bhp, g_b_hi);
    cudaGetSymbolAddress((void**)&blp, g_b_lo);
    cudaGetSymbolAddress((void**)&qh, g_q_hi);
    cudaGetSymbolAddress((void**)&ql, g_q_lo);
    cudaGetSymbolAddress((void**)&kh, g_k_hi);
    cudaGetSymbolAddress((void**)&kl, g_k_lo);
    cudaGetSymbolAddress((void**)&vth, g_vt_hi);
    cudaGetSymbolAddress((void**)&vtl, g_vt_lo);

    cudaFuncSetAttribute(gemm_mma3, cudaFuncAttributeMaxDynamicSharedMemorySize, GEMM_SMEM);
    cudaFuncSetAttribute(attn_mma, cudaFuncAttributeMaxDynamicSharedMemorySize, ATTN_SMEM);

    // 1. split x -> a planes, w_in -> b planes
    split2_kernel<<<(ROWS * HID / 4 + 255) / 256, 256>>>(x, ah, al, ROWS * HID / 4);
    split2_kernel<<<(QKV_W * HID / 4 + 255) / 256, 256>>>(w_in, bhp, blp, QKV_W * HID / 4);

    // 2. QKV = x @ w_in^T
    gemm_mma3<<<(ROWS / BM) * (QKV_W / BN), 512, GEMM_SMEM>>>(ah, al, bhp, blp, qkv, ROWS, QKV_W);

    // 3. tables + norm/rope -> bf16 planes; V transpose/split
    rope_table_kernel<<<(S_ * HALF + 255) / 256, 256>>>();
    normrope_kernel<<<ROWS, 256>>>(qkv, qnw, knw, qh, ql, kh, kl);
    vtrans_kernel<<<dim3(ROWS / 32, HID / 32), 256>>>(qkv, vth, vtl);

    // 4. attention -> a planes (gemm2 A operand)
    attn_mma<<<dim3(S_ / 128, B_ * NH), 256, ATTN_SMEM>>>(qh, ql, kh, kl, vth, vtl, ah, al);

    // 5. w_out -> b planes; out = O @ w_out^T
    split2_kernel<<<(HID * HID / 4 + 255) / 256, 256>>>(w_out, bhp, blp, HID * HID / 4);
    gemm_mma3<<<(ROWS / BM) * (HID / BN), 512, GEMM_SMEM>>>(ah, al, bhp, blp, out, ROWS, HID);
}